// round 1
// baseline (speedup 1.0000x reference)
#include <cuda_runtime.h>

// Problem constants (fixed shapes)
#define BQ  16
#define CC  256
#define HH  48
#define WW  48
#define NN  (HH*WW)      // 2304
#define KNN 8
#define TILE 128
#define KC   16
#define SCP  (TILE + 4)  // padded score row (float4-aligned, reduces bank conflicts)

// Scratch (device globals; no allocation allowed)
__device__ float g_nodesT[BQ * NN * CC];  // [B][N][C] transposed features
__device__ float g_sq[BQ * NN];           // squared norms
__device__ int   g_knn[BQ * NN * KNN];    // top-8 neighbor indices

// ---------------------------------------------------------------------------
// Kernel 1: transpose F[b][c][n] -> nodesT[b][n][c]
// ---------------------------------------------------------------------------
__global__ void k_transpose(const float* __restrict__ F) {
    __shared__ float t[32][33];
    int b  = blockIdx.z;
    int n0 = blockIdx.x * 32;
    int c0 = blockIdx.y * 32;
    const float* Fb = F + (size_t)b * CC * NN;
    int tx = threadIdx.x, ty = threadIdx.y;  // 32 x 8
#pragma unroll
    for (int i = 0; i < 32; i += 8)
        t[ty + i][tx] = Fb[(size_t)(c0 + ty + i) * NN + n0 + tx];
    __syncthreads();
    float* out = g_nodesT + (size_t)b * NN * CC;
#pragma unroll
    for (int i = 0; i < 32; i += 8)
        out[(size_t)(n0 + ty + i) * CC + c0 + tx] = t[tx][ty + i];
}

// ---------------------------------------------------------------------------
// Kernel 2: squared norms sq[b][n] = sum_c F[b][c][n]^2
// ---------------------------------------------------------------------------
__global__ void k_sq(const float* __restrict__ F) {
    int gid = blockIdx.x * blockDim.x + threadIdx.x;
    if (gid >= BQ * NN) return;
    int b = gid / NN, n = gid % NN;
    const float* Fb = F + (size_t)b * CC * NN + n;
    float s = 0.f;
#pragma unroll 8
    for (int c = 0; c < CC; ++c) {
        float v = Fb[(size_t)c * NN];
        s += v * v;
    }
    g_sq[gid] = s;
}

// ---------------------------------------------------------------------------
// Kernel 3: fused Gram (X X^T) + top-8 nearest neighbors per row.
// Block computes a 128-row stripe across all N columns, tile by tile.
// SGEMM-style: 128x128 tile, 8x8 micro-tiles, k-chunks of 16.
// Scores staged through smem; 2 threads per row keep running top-8 in regs.
// Dynamic smem layout (floats):
//   As[KC][TILE]  @ 0          (2048)
//   Bs[KC][TILE]  @ 2048       (2048)
//   sqs[TILE]     @ 4096       (128)
//   Sc[TILE][SCP] @ 4224       (128*132 = 16896)
// total = 21120 floats = 84480 bytes
// ---------------------------------------------------------------------------
__global__ __launch_bounds__(256, 2) void k_gram_topk(const float* __restrict__ F) {
    extern __shared__ float sm[];
    float* As  = sm;
    float* Bs  = sm + KC * TILE;
    float* sqs = sm + 2 * KC * TILE;
    float* Sc  = sm + 2 * KC * TILE + TILE;

    const int b  = blockIdx.y;
    const int i0 = blockIdx.x * TILE;
    const float* Fb = F + (size_t)b * CC * NN;
    const int tid = threadIdx.x;
    const int tx = tid & 15, ty = tid >> 4;

    // per-thread running top-8 (sorted descending: [0]=worst, [7]=best)
    float ts[KNN];
    int   ti[KNN];
#pragma unroll
    for (int k = 0; k < KNN; ++k) { ts[k] = 3.0e38f; ti[k] = 0; }
    const int srow  = tid >> 1;   // scan row 0..127
    const int shalf = tid & 1;    // scan half (cols 0..63 / 64..127)
    const int ig    = i0 + srow;  // global row index (self-exclusion)

    for (int j0 = 0; j0 < NN; j0 += TILE) {
        float acc[8][8];
#pragma unroll
        for (int r = 0; r < 8; ++r)
#pragma unroll
            for (int c = 0; c < 8; ++c) acc[r][c] = 0.f;

        if (tid < TILE) sqs[tid] = g_sq[b * NN + j0 + tid];

        for (int kc = 0; kc < CC; kc += KC) {
#pragma unroll
            for (int v = 0; v < 2; ++v) {
                int t = tid + v * 256;
                int c = t >> 5;
                int x = (t & 31) << 2;
                *(float4*)&As[c * TILE + x] =
                    *(const float4*)&Fb[(size_t)(kc + c) * NN + i0 + x];
                *(float4*)&Bs[c * TILE + x] =
                    *(const float4*)&Fb[(size_t)(kc + c) * NN + j0 + x];
            }
            __syncthreads();
#pragma unroll
            for (int kk = 0; kk < KC; ++kk) {
                float a[8], bb[8];
                *(float4*)&a[0]  = *(float4*)&As[kk * TILE + ty * 8];
                *(float4*)&a[4]  = *(float4*)&As[kk * TILE + ty * 8 + 4];
                *(float4*)&bb[0] = *(float4*)&Bs[kk * TILE + tx * 8];
                *(float4*)&bb[4] = *(float4*)&Bs[kk * TILE + tx * 8 + 4];
#pragma unroll
                for (int r = 0; r < 8; ++r)
#pragma unroll
                    for (int c = 0; c < 8; ++c)
                        acc[r][c] += a[r] * bb[c];
            }
            __syncthreads();
        }

        // stage scores to smem
#pragma unroll
        for (int r = 0; r < 8; ++r) {
            int row = ty * 8 + r;
            *(float4*)&Sc[row * SCP + tx * 8] =
                make_float4(acc[r][0], acc[r][1], acc[r][2], acc[r][3]);
            *(float4*)&Sc[row * SCP + tx * 8 + 4] =
                make_float4(acc[r][4], acc[r][5], acc[r][6], acc[r][7]);
        }
        __syncthreads();

        // scan: key = sq[j] - 2*dot  (sq[i] constant per row, irrelevant to rank)
        const float* srcrow = &Sc[srow * SCP + shalf * 64];
        const float* sqrow  = &sqs[shalf * 64];
        const int jbase = j0 + shalf * 64;
        for (int s = 0; s < 64; ++s) {
            int j = jbase + s;
            float key = sqrow[s] - 2.0f * srcrow[s];
            if (j != ig && key < ts[0]) {
                ts[0] = key; ti[0] = j;
#pragma unroll
                for (int t2 = 0; t2 < KNN - 1; ++t2) {
                    if (ts[t2] < ts[t2 + 1]) {
                        float tf = ts[t2]; ts[t2] = ts[t2 + 1]; ts[t2 + 1] = tf;
                        int   tn = ti[t2]; ti[t2] = ti[t2 + 1]; ti[t2 + 1] = tn;
                    }
                }
            }
        }
        __syncthreads();  // protect Sc/sqs before next tile overwrites
    }

    // merge the two halves of each row (reuse As/Bs region)
    float* ms = As;                    // [128][2][8] scores
    int*   mi = (int*)(As + 2048);     // [128][2][8] indices (Bs region)
#pragma unroll
    for (int k = 0; k < KNN; ++k) {
        ms[(srow * 2 + shalf) * KNN + k] = ts[k];
        mi[(srow * 2 + shalf) * KNN + k] = ti[k];
    }
    __syncthreads();
    if (tid < TILE) {
        int row = tid;
        float fs[KNN]; int fi[KNN];
#pragma unroll
        for (int k = 0; k < KNN; ++k) { fs[k] = 3.0e38f; fi[k] = 0; }
        for (int q = 0; q < 2 * KNN; ++q) {
            float cs = ms[row * 2 * KNN + q];
            int   cj = mi[row * 2 * KNN + q];
            if (cs < fs[0]) {
                fs[0] = cs; fi[0] = cj;
#pragma unroll
                for (int t2 = 0; t2 < KNN - 1; ++t2) {
                    if (fs[t2] < fs[t2 + 1]) {
                        float tf = fs[t2]; fs[t2] = fs[t2 + 1]; fs[t2 + 1] = tf;
                        int   tn = fi[t2]; fi[t2] = fi[t2 + 1]; fi[t2 + 1] = tn;
                    }
                }
            }
        }
        int base = (b * NN + i0 + row) * KNN;
#pragma unroll
        for (int k = 0; k < KNN; ++k) g_knn[base + k] = fi[k];
    }
}

// ---------------------------------------------------------------------------
// Kernel 4: aggregation (grid + knn mean) + residual + LayerNorm + write out.
// One warp per node; 8 nodes per block. Channels: 8 regs/lane (C=256).
// ---------------------------------------------------------------------------
__global__ void k_aggregate(const float* __restrict__ gamma,
                            const float* __restrict__ beta,
                            float* __restrict__ out) {
    const int b    = blockIdx.y;
    const int wid  = threadIdx.x >> 5;
    const int lane = threadIdx.x & 31;
    const int n0   = blockIdx.x * 8;
    const int n    = n0 + wid;
    const int h = n / WW, w = n % WW;
    const float* Nb = g_nodesT + (size_t)b * NN * CC;

    float xi[8], acc[8];
#pragma unroll
    for (int r = 0; r < 8; ++r) {
        xi[r]  = Nb[(size_t)n * CC + r * 32 + lane];
        acc[r] = 0.f;
    }
    int cnt = KNN;
    if (w > 0)      { const float* p = Nb + (size_t)(n - 1)  * CC;
#pragma unroll
        for (int r = 0; r < 8; ++r) acc[r] += p[r * 32 + lane]; cnt++; }
    if (w < WW - 1) { const float* p = Nb + (size_t)(n + 1)  * CC;
#pragma unroll
        for (int r = 0; r < 8; ++r) acc[r] += p[r * 32 + lane]; cnt++; }
    if (h > 0)      { const float* p = Nb + (size_t)(n - WW) * CC;
#pragma unroll
        for (int r = 0; r < 8; ++r) acc[r] += p[r * 32 + lane]; cnt++; }
    if (h < HH - 1) { const float* p = Nb + (size_t)(n + WW) * CC;
#pragma unroll
        for (int r = 0; r < 8; ++r) acc[r] += p[r * 32 + lane]; cnt++; }

    const int* kk = g_knn + (size_t)(b * NN + n) * KNN;
#pragma unroll
    for (int k = 0; k < KNN; ++k) {
        const float* p = Nb + (size_t)kk[k] * CC;
#pragma unroll
        for (int r = 0; r < 8; ++r) acc[r] += p[r * 32 + lane];
    }

    const float inv = 1.0f / (float)cnt;
    float y[8];
#pragma unroll
    for (int r = 0; r < 8; ++r) y[r] = acc[r] * inv + xi[r];

    // mean
    float s = 0.f;
#pragma unroll
    for (int r = 0; r < 8; ++r) s += y[r];
#pragma unroll
    for (int o = 16; o > 0; o >>= 1) s += __shfl_xor_sync(0xffffffffu, s, o);
    const float mu = s * (1.0f / CC);
    // variance
    float v = 0.f;
#pragma unroll
    for (int r = 0; r < 8; ++r) { float d = y[r] - mu; v += d * d; }
#pragma unroll
    for (int o = 16; o > 0; o >>= 1) v += __shfl_xor_sync(0xffffffffu, v, o);
    const float rs = rsqrtf(v * (1.0f / CC) + 1e-5f);

    __shared__ float st[8][CC];
#pragma unroll
    for (int r = 0; r < 8; ++r) {
        int c = r * 32 + lane;
        st[wid][c] = (y[r] - mu) * rs * gamma[c] + beta[c];
    }
    __syncthreads();

    // coalesced-ish write: thread = channel, 8 consecutive n per thread (32B sectors)
    const int c = threadIdx.x;
    float4 v0 = make_float4(st[0][c], st[1][c], st[2][c], st[3][c]);
    float4 v1 = make_float4(st[4][c], st[5][c], st[6][c], st[7][c]);
    size_t o = (size_t)b * CC * NN + (size_t)c * NN + n0;
    *(float4*)&out[o]     = v0;
    *(float4*)&out[o + 4] = v1;
}

// ---------------------------------------------------------------------------
extern "C" void kernel_launch(void* const* d_in, const int* in_sizes, int n_in,
                              void* d_out, int out_size) {
    const float* F     = (const float*)d_in[0];
    const float* gamma = (const float*)d_in[1];
    const float* beta  = (const float*)d_in[2];
    float* out = (float*)d_out;

    (void)in_sizes; (void)n_in; (void)out_size;

    k_transpose<<<dim3(NN / 32, CC / 32, BQ), dim3(32, 8)>>>(F);
    k_sq<<<(BQ * NN + 255) / 256, 256>>>(F);

    const size_t smem = (size_t)(2 * KC * TILE + TILE + TILE * SCP) * sizeof(float);
    cudaFuncSetAttribute(k_gram_topk, cudaFuncAttributeMaxDynamicSharedMemorySize, (int)smem);
    k_gram_topk<<<dim3(NN / TILE, BQ), 256, smem>>>(F);

    k_aggregate<<<dim3(NN / 8, BQ), 256>>>(gamma, beta, out);
}

// round 4
// speedup vs baseline: 1.6320x; 1.6320x over previous
#include <cuda_runtime.h>
#include <cstdint>

// Problem constants (fixed shapes)
#define BQ  16
#define CC  256
#define HH  48
#define WW  48
#define NN  (HH*WW)      // 2304
#define KNN 8
#define KB  12           // per-thread candidate buffer (2 threads/row -> 24)
#define NCAND (2*KB)     // 24 candidates per row
#define TILE 128         // M and N tile
#define NTILES (NN/TILE) // 18
#define KC2 32           // K chunk
#define APAD 36          // padded row length (floats) for A/B chunk smem
#define SCP 132          // padded score row

// Scratch (device globals; no allocation allowed)
__device__ float g_nodesT[BQ * NN * CC];   // [B][N][C] transposed features
__device__ float g_sq[BQ * NN];            // squared norms
__device__ int   g_cand[BQ * NN * NCAND];  // tf32-filtered candidates
__device__ int   g_knn[BQ * NN * KNN];     // exact top-8 neighbor indices

__device__ __forceinline__ uint32_t f2tf32(float f) {
    uint32_t r;
    asm("cvt.rna.tf32.f32 %0, %1;" : "=r"(r) : "f"(f));
    return r;
}

// ---------------------------------------------------------------------------
// Kernel 1: transpose F[b][c][n] -> nodesT[b][n][c]
// ---------------------------------------------------------------------------
__global__ void k_transpose(const float* __restrict__ F) {
    __shared__ float t[32][33];
    int b  = blockIdx.z;
    int n0 = blockIdx.x * 32;
    int c0 = blockIdx.y * 32;
    const float* Fb = F + (size_t)b * CC * NN;
    int tx = threadIdx.x, ty = threadIdx.y;  // 32 x 8
#pragma unroll
    for (int i = 0; i < 32; i += 8)
        t[ty + i][tx] = Fb[(size_t)(c0 + ty + i) * NN + n0 + tx];
    __syncthreads();
    float* out = g_nodesT + (size_t)b * NN * CC;
#pragma unroll
    for (int i = 0; i < 32; i += 8)
        out[(size_t)(n0 + ty + i) * CC + c0 + tx] = t[tx][ty + i];
}

// ---------------------------------------------------------------------------
// Kernel 2: squared norms sq[b][n]
// ---------------------------------------------------------------------------
__global__ void k_sq(const float* __restrict__ F) {
    int gid = blockIdx.x * blockDim.x + threadIdx.x;
    if (gid >= BQ * NN) return;
    int b = gid / NN, n = gid % NN;
    const float* Fb = F + (size_t)b * CC * NN + n;
    float s = 0.f;
#pragma unroll 8
    for (int c = 0; c < CC; ++c) {
        float v = Fb[(size_t)c * NN];
        s += v * v;
    }
    g_sq[gid] = s;
}

// ---------------------------------------------------------------------------
// Kernel 3: tf32 mma.sync Gram + per-half top-12 candidate filter.
// CTA = (sample b, 128-row stripe), 256 threads = 8 warps (4 warp_m x 2 warp_n).
// Warp tile 32x64; mma m16n8k8: 2 m-subtiles x 8 n-subtiles, acc[2][8][4] f32.
// K loop: chunks of 32 staged in smem (As[128][36], Bs[128][36]).
// After K loop: stage 128x128 scores to smem, 2 threads/row keep top-12 each.
// ---------------------------------------------------------------------------
__global__ __launch_bounds__(256, 2) void k_gram_topk_mma() {
    extern __shared__ float sm[];
    float* As  = sm;                       // [128][36]
    float* Bs  = sm + 128 * APAD;          // [128][36]
    float* Sc  = sm + 2 * 128 * APAD;      // [128][132]
    float* sqs = sm + 2 * 128 * APAD + 128 * SCP;  // [128]

    const int b   = blockIdx.y;
    const int i0  = blockIdx.x * TILE;
    const int tid = threadIdx.x;
    const int wid  = tid >> 5;
    const int lane = tid & 31;
    const int wm = wid >> 1;       // 0..3
    const int wn = wid & 1;        // 0..1
    const int grp = lane >> 2;     // 0..7
    const int tig = lane & 3;      // 0..3
    const float* Nb = g_nodesT + (size_t)b * NN * CC;

    const int ldm = tid >> 1;      // row 0..127 (2 threads per row)
    const int lds = (tid & 1) * 16;

    // per-thread top-12 ([0]=worst)
    float ts[KB];
    int   ti[KB];
#pragma unroll
    for (int k = 0; k < KB; ++k) { ts[k] = 3.0e38f; ti[k] = 0; }
    const int srow  = tid >> 1;
    const int shalf = tid & 1;
    const int ig    = i0 + srow;

    for (int jt = 0; jt < NTILES; ++jt) {
        const int j0 = jt * TILE;
        if (tid < TILE) sqs[tid] = g_sq[b * NN + j0 + tid];

        float acc[2][8][4];
#pragma unroll
        for (int mt = 0; mt < 2; ++mt)
#pragma unroll
            for (int nt = 0; nt < 8; ++nt)
#pragma unroll
                for (int q = 0; q < 4; ++q) acc[mt][nt][q] = 0.f;

        for (int kc = 0; kc < CC; kc += KC2) {
            {
                const float* ap = Nb + (size_t)(i0 + ldm) * CC + kc + lds;
                const float* bp = Nb + (size_t)(j0 + ldm) * CC + kc + lds;
                float* ad = As + ldm * APAD + lds;
                float* bd = Bs + ldm * APAD + lds;
#pragma unroll
                for (int q = 0; q < 4; ++q) {
                    *(float4*)(ad + q * 4) = *(const float4*)(ap + q * 4);
                    *(float4*)(bd + q * 4) = *(const float4*)(bp + q * 4);
                }
            }
            __syncthreads();

#pragma unroll
            for (int ks = 0; ks < 4; ++ks) {
                const int kb = ks * 8;
                uint32_t bf[8][2];
#pragma unroll
                for (int nt = 0; nt < 8; ++nt) {
                    const int col = wn * 64 + nt * 8 + grp;
                    bf[nt][0] = f2tf32(Bs[col * APAD + kb + tig]);
                    bf[nt][1] = f2tf32(Bs[col * APAD + kb + tig + 4]);
                }
#pragma unroll
                for (int mt = 0; mt < 2; ++mt) {
                    const int row = wm * 32 + mt * 16 + grp;
                    uint32_t a0 = f2tf32(As[row * APAD + kb + tig]);
                    uint32_t a1 = f2tf32(As[(row + 8) * APAD + kb + tig]);
                    uint32_t a2 = f2tf32(As[row * APAD + kb + tig + 4]);
                    uint32_t a3 = f2tf32(As[(row + 8) * APAD + kb + tig + 4]);
#pragma unroll
                    for (int nt = 0; nt < 8; ++nt) {
                        asm volatile(
                            "mma.sync.aligned.m16n8k8.row.col.f32.tf32.tf32.f32 "
                            "{%0,%1,%2,%3}, {%4,%5,%6,%7}, {%8,%9}, {%0,%1,%2,%3};"
                            : "+f"(acc[mt][nt][0]), "+f"(acc[mt][nt][1]),
                              "+f"(acc[mt][nt][2]), "+f"(acc[mt][nt][3])
                            : "r"(a0), "r"(a1), "r"(a2), "r"(a3),
                              "r"(bf[nt][0]), "r"(bf[nt][1]));
                    }
                }
            }
            __syncthreads();
        }

        // stage scores to smem (float2 per c-pair)
#pragma unroll
        for (int mt = 0; mt < 2; ++mt) {
            const int r0 = wm * 32 + mt * 16 + grp;
#pragma unroll
            for (int nt = 0; nt < 8; ++nt) {
                const int c0 = wn * 64 + nt * 8 + 2 * tig;
                *(float2*)&Sc[r0 * SCP + c0] =
                    make_float2(acc[mt][nt][0], acc[mt][nt][1]);
                *(float2*)&Sc[(r0 + 8) * SCP + c0] =
                    make_float2(acc[mt][nt][2], acc[mt][nt][3]);
            }
        }
        __syncthreads();

        // scan: key = sq[j] - 2*dot (sq[i] constant per row)
        const float* srcrow = &Sc[srow * SCP + shalf * 64];
        const float* sqrow  = &sqs[shalf * 64];
        const int jbase = j0 + shalf * 64;
        for (int s = 0; s < 64; ++s) {
            int j = jbase + s;
            float key = sqrow[s] - 2.0f * srcrow[s];
            if (j != ig && key < ts[0]) {
                ts[0] = key; ti[0] = j;
#pragma unroll
                for (int t2 = 0; t2 < KB - 1; ++t2) {
                    if (ts[t2] < ts[t2 + 1]) {
                        float tf = ts[t2]; ts[t2] = ts[t2 + 1]; ts[t2 + 1] = tf;
                        int   tn = ti[t2]; ti[t2] = ti[t2 + 1]; ti[t2 + 1] = tn;
                    }
                }
            }
        }
        __syncthreads();  // Sc/sqs reusable next tile
    }

    // write 12 candidates per half directly (no merge; rescore picks exact top-8)
    {
        int base = ((b * NN + ig) * 2 + shalf) * KB;
#pragma unroll
        for (int k = 0; k < KB; ++k) g_cand[base + k] = ti[k];
    }
}

// ---------------------------------------------------------------------------
// Kernel 3b: exact fp32 rescore of 24 candidates -> top-8.
// One warp per row. Lane l owns channels [8l, 8l+8).
// ---------------------------------------------------------------------------
__global__ __launch_bounds__(128) void k_rescore() {
    const int warp = threadIdx.x >> 5;
    const int lane = threadIdx.x & 31;
    const int n = blockIdx.x * 4 + warp;
    const int b = blockIdx.y;
    const float* Nb = g_nodesT + (size_t)b * NN * CC;

    const float* xi = Nb + (size_t)n * CC + lane * 8;
    float4 x0 = *(const float4*)xi;
    float4 x1 = *(const float4*)(xi + 4);

    int cand = (lane < NCAND) ? g_cand[(b * NN + n) * NCAND + lane] : 0;

    float mykey = 3.0e38f;
    int   myidx = 0;
#pragma unroll
    for (int k = 0; k < NCAND; ++k) {
        int j = __shfl_sync(0xffffffffu, cand, k);
        const float* xj = Nb + (size_t)j * CC + lane * 8;
        float4 y0 = *(const float4*)xj;
        float4 y1 = *(const float4*)(xj + 4);
        float p = x0.x * y0.x + x0.y * y0.y + x0.z * y0.z + x0.w * y0.w
                + x1.x * y1.x + x1.y * y1.y + x1.z * y1.z + x1.w * y1.w;
#pragma unroll
        for (int o = 16; o > 0; o >>= 1) p += __shfl_xor_sync(0xffffffffu, p, o);
        float key = g_sq[b * NN + j] - 2.0f * p;
        if (lane == k) { mykey = key; myidx = j; }
    }

    // extract 8 smallest (duplicate candidates impossible: disjoint halves)
    int keep = 0;
#pragma unroll
    for (int t = 0; t < KNN; ++t) {
        float v = mykey;
#pragma unroll
        for (int o = 16; o > 0; o >>= 1) v = fminf(v, __shfl_xor_sync(0xffffffffu, v, o));
        unsigned m = __ballot_sync(0xffffffffu, mykey == v);
        int src = __ffs(m) - 1;
        int sel = __shfl_sync(0xffffffffu, myidx, src);
        if (lane == t) keep = sel;
        if (lane == src) mykey = 3.0e38f;
    }
    if (lane < KNN) g_knn[(b * NN + n) * KNN + lane] = keep;
}

// ---------------------------------------------------------------------------
// Kernel 4: aggregation (grid + knn mean) + residual + LayerNorm + write out.
// ---------------------------------------------------------------------------
__global__ void k_aggregate(const float* __restrict__ gamma,
                            const float* __restrict__ beta,
                            float* __restrict__ out) {
    const int b    = blockIdx.y;
    const int wid  = threadIdx.x >> 5;
    const int lane = threadIdx.x & 31;
    const int n0   = blockIdx.x * 8;
    const int n    = n0 + wid;
    const int h = n / WW, w = n % WW;
    const float* Nb = g_nodesT + (size_t)b * NN * CC;

    float xi[8], acc[8];
#pragma unroll
    for (int r = 0; r < 8; ++r) {
        xi[r]  = Nb[(size_t)n * CC + r * 32 + lane];
        acc[r] = 0.f;
    }
    int cnt = KNN;
    if (w > 0)      { const float* p = Nb + (size_t)(n - 1)  * CC;
#pragma unroll
        for (int r = 0; r < 8; ++r) acc[r] += p[r * 32 + lane]; cnt++; }
    if (w < WW - 1) { const float* p = Nb + (size_t)(n + 1)  * CC;
#pragma unroll
        for (int r = 0; r < 8; ++r) acc[r] += p[r * 32 + lane]; cnt++; }
    if (h > 0)      { const float* p = Nb + (size_t)(n - WW) * CC;
#pragma unroll
        for (int r = 0; r < 8; ++r) acc[r] += p[r * 32 + lane]; cnt++; }
    if (h < HH - 1) { const float* p = Nb + (size_t)(n + WW) * CC;
#pragma unroll
        for (int r = 0; r < 8; ++r) acc[r] += p[r * 32 + lane]; cnt++; }

    const int* kk = g_knn + (size_t)(b * NN + n) * KNN;
#pragma unroll
    for (int k = 0; k < KNN; ++k) {
        const float* p = Nb + (size_t)kk[k] * CC;
#pragma unroll
        for (int r = 0; r < 8; ++r) acc[r] += p[r * 32 + lane];
    }

    const float inv = 1.0f / (float)cnt;
    float y[8];
#pragma unroll
    for (int r = 0; r < 8; ++r) y[r] = acc[r] * inv + xi[r];

    float s = 0.f;
#pragma unroll
    for (int r = 0; r < 8; ++r) s += y[r];
#pragma unroll
    for (int o = 16; o > 0; o >>= 1) s += __shfl_xor_sync(0xffffffffu, s, o);
    const float mu = s * (1.0f / CC);
    float v = 0.f;
#pragma unroll
    for (int r = 0; r < 8; ++r) { float d = y[r] - mu; v += d * d; }
#pragma unroll
    for (int o = 16; o > 0; o >>= 1) v += __shfl_xor_sync(0xffffffffu, v, o);
    const float rs = rsqrtf(v * (1.0f / CC) + 1e-5f);

    __shared__ float st[8][CC];
#pragma unroll
    for (int r = 0; r < 8; ++r) {
        int c = r * 32 + lane;
        st[wid][c] = (y[r] - mu) * rs * gamma[c] + beta[c];
    }
    __syncthreads();

    const int c = threadIdx.x;
    float4 v0 = make_float4(st[0][c], st[1][c], st[2][c], st[3][c]);
    float4 v1 = make_float4(st[4][c], st[5][c], st[6][c], st[7][c]);
    size_t o = (size_t)b * CC * NN + (size_t)c * NN + n0;
    *(float4*)&out[o]     = v0;
    *(float4*)&out[o + 4] = v1;
}

// ---------------------------------------------------------------------------
extern "C" void kernel_launch(void* const* d_in, const int* in_sizes, int n_in,
                              void* d_out, int out_size) {
    const float* F     = (const float*)d_in[0];
    const float* gamma = (const float*)d_in[1];
    const float* beta  = (const float*)d_in[2];
    float* out = (float*)d_out;
    (void)in_sizes; (void)n_in; (void)out_size;

    k_transpose<<<dim3(NN / 32, CC / 32, BQ), dim3(32, 8)>>>(F);
    k_sq<<<(BQ * NN + 255) / 256, 256>>>(F);

    const size_t smem = (size_t)(2 * 128 * APAD + 128 * SCP + 128) * sizeof(float);
    cudaFuncSetAttribute(k_gram_topk_mma,
                         cudaFuncAttributeMaxDynamicSharedMemorySize, (int)smem);
    k_gram_topk_mma<<<dim3(NTILES, BQ), 256, smem>>>();

    k_rescore<<<dim3(NN / 4, BQ), 128>>>();

    k_aggregate<<<dim3(NN / 8, BQ), 256>>>(gamma, beta, out);
}

// round 5
// speedup vs baseline: 1.7146x; 1.0506x over previous
#include <cuda_runtime.h>
#include <cuda_bf16.h>
#include <cstdint>

// Problem constants (fixed shapes)
#define BQ  16
#define CC  256
#define HH  48
#define WW  48
#define NN  (HH*WW)      // 2304
#define KNN 8
#define KB  16           // per-thread candidate buffer (2 threads/row -> 32)
#define NCAND (2*KB)     // 32 candidates per row == warp size
#define TILE 128         // M and N tile
#define NTILES (NN/TILE) // 18
#define KCB 64           // K chunk (bf16), 4 k16 steps
#define BPADW 36         // padded row length in 32-bit words (72 bf16)
#define SCP 132          // padded score row (floats)

// Scratch (device globals; no allocation allowed)
__device__ float          g_nodesT[BQ * NN * CC];   // [B][N][C] fp32 features
__device__ __nv_bfloat16  g_bf16[BQ * NN * CC];     // bf16 copy for filter GEMM
__device__ float          g_sq[BQ * NN];            // squared norms (fp32)
__device__ int            g_cand[BQ * NN * NCAND];  // bf16-filtered candidates

// ---------------------------------------------------------------------------
// Kernel 1: transpose F[b][c][n] -> nodesT[b][n][c] (fp32 + bf16 copies)
// ---------------------------------------------------------------------------
__global__ void k_transpose(const float* __restrict__ F) {
    __shared__ float t[32][33];
    int b  = blockIdx.z;
    int n0 = blockIdx.x * 32;
    int c0 = blockIdx.y * 32;
    const float* Fb = F + (size_t)b * CC * NN;
    int tx = threadIdx.x, ty = threadIdx.y;  // 32 x 8
#pragma unroll
    for (int i = 0; i < 32; i += 8)
        t[ty + i][tx] = Fb[(size_t)(c0 + ty + i) * NN + n0 + tx];
    __syncthreads();
    float* out = g_nodesT + (size_t)b * NN * CC;
    __nv_bfloat16* outb = g_bf16 + (size_t)b * NN * CC;
#pragma unroll
    for (int i = 0; i < 32; i += 8) {
        float v = t[tx][ty + i];
        size_t o = (size_t)(n0 + ty + i) * CC + c0 + tx;
        out[o]  = v;
        outb[o] = __float2bfloat16(v);
    }
}

// ---------------------------------------------------------------------------
// Kernel 2: squared norms sq[b][n]
// ---------------------------------------------------------------------------
__global__ void k_sq(const float* __restrict__ F) {
    int gid = blockIdx.x * blockDim.x + threadIdx.x;
    if (gid >= BQ * NN) return;
    int b = gid / NN, n = gid % NN;
    const float* Fb = F + (size_t)b * CC * NN + n;
    float s = 0.f;
#pragma unroll 8
    for (int c = 0; c < CC; ++c) {
        float v = Fb[(size_t)c * NN];
        s += v * v;
    }
    g_sq[gid] = s;
}

// ---------------------------------------------------------------------------
// Kernel 3: bf16 mma.m16n8k16 Gram + per-half top-16 candidate filter.
// CTA = (sample b, 128-row stripe), 256 threads = 8 warps (4 warp_m x 2 warp_n).
// Warp tile 32x64; 2 m-subtiles x 8 n-subtiles, acc[2][8][4] f32.
// K loop: chunks of 64 bf16 staged in smem (padded rows of 72 bf16 = 36 words).
// After K loop: stage 128x128 scores to smem, 2 threads/row keep top-16 each.
// smem bytes: As 18432 | Bs 18432 | Sc 67584 | sqs 512 = 104,960
// ---------------------------------------------------------------------------
#define SMB_AS 0
#define SMB_BS 18432
#define SMB_SC 36864
#define SMB_SQ (36864 + 67584)
#define SMB_TOT (SMB_SQ + 512)

__global__ __launch_bounds__(256, 2) void k_gram_topk_mma() {
    extern __shared__ unsigned char smraw[];
    uint32_t* As32 = (uint32_t*)(smraw + SMB_AS);   // [128][36] words (72 bf16)
    uint32_t* Bs32 = (uint32_t*)(smraw + SMB_BS);
    float*    Sc   = (float*)(smraw + SMB_SC);      // [128][132]
    float*    sqs  = (float*)(smraw + SMB_SQ);      // [128]

    const int b   = blockIdx.y;
    const int i0  = blockIdx.x * TILE;
    const int tid = threadIdx.x;
    const int wid  = tid >> 5;
    const int lane = tid & 31;
    const int wm = wid >> 1;       // 0..3
    const int wn = wid & 1;        // 0..1
    const int grp = lane >> 2;     // 0..7
    const int tig = lane & 3;      // 0..3
    const __nv_bfloat16* Hb = g_bf16 + (size_t)b * NN * CC;

    const int ldr = tid >> 1;            // row 0..127 (2 threads per row)
    const int ldh = (tid & 1) * 32;      // bf16 offset within chunk row

    // per-thread top-16 ([0]=worst)
    float ts[KB];
    int   ti[KB];
#pragma unroll
    for (int k = 0; k < KB; ++k) { ts[k] = 3.0e38f; ti[k] = 0; }
    const int srow  = tid >> 1;
    const int shalf = tid & 1;
    const int ig    = i0 + srow;

    for (int jt = 0; jt < NTILES; ++jt) {
        const int j0 = jt * TILE;
        if (tid < TILE) sqs[tid] = g_sq[b * NN + j0 + tid];

        float acc[2][8][4];
#pragma unroll
        for (int mt = 0; mt < 2; ++mt)
#pragma unroll
            for (int nt = 0; nt < 8; ++nt)
#pragma unroll
                for (int q = 0; q < 4; ++q) acc[mt][nt][q] = 0.f;

        for (int kc = 0; kc < CC; kc += KCB) {
            // load A,B chunks [128][64] bf16 into padded smem
            {
                const uint4* ap = (const uint4*)(Hb + (size_t)(i0 + ldr) * CC + kc + ldh);
                const uint4* bp = (const uint4*)(Hb + (size_t)(j0 + ldr) * CC + kc + ldh);
                uint4* ad = (uint4*)(As32 + ldr * BPADW + ldh / 2);
                uint4* bd = (uint4*)(Bs32 + ldr * BPADW + ldh / 2);
#pragma unroll
                for (int q = 0; q < 4; ++q) { ad[q] = ap[q]; bd[q] = bp[q]; }
            }
            __syncthreads();

#pragma unroll
            for (int ks = 0; ks < 4; ++ks) {
                const int kw = ks * 8;  // word offset of this k16 step
#pragma unroll
                for (int mt = 0; mt < 2; ++mt) {
                    const int row = wm * 32 + mt * 16 + grp;
                    uint32_t a0 = As32[row * BPADW + kw + tig];
                    uint32_t a1 = As32[(row + 8) * BPADW + kw + tig];
                    uint32_t a2 = As32[row * BPADW + kw + 4 + tig];
                    uint32_t a3 = As32[(row + 8) * BPADW + kw + 4 + tig];
#pragma unroll
                    for (int nt = 0; nt < 8; ++nt) {
                        const int col = wn * 64 + nt * 8 + grp;
                        uint32_t b0 = Bs32[col * BPADW + kw + tig];
                        uint32_t b1 = Bs32[col * BPADW + kw + 4 + tig];
                        asm volatile(
                            "mma.sync.aligned.m16n8k16.row.col.f32.bf16.bf16.f32 "
                            "{%0,%1,%2,%3}, {%4,%5,%6,%7}, {%8,%9}, {%0,%1,%2,%3};"
                            : "+f"(acc[mt][nt][0]), "+f"(acc[mt][nt][1]),
                              "+f"(acc[mt][nt][2]), "+f"(acc[mt][nt][3])
                            : "r"(a0), "r"(a1), "r"(a2), "r"(a3),
                              "r"(b0), "r"(b1));
                    }
                }
            }
            __syncthreads();
        }

        // stage scores to smem (float2 per c-pair)
#pragma unroll
        for (int mt = 0; mt < 2; ++mt) {
            const int r0 = wm * 32 + mt * 16 + grp;
#pragma unroll
            for (int nt = 0; nt < 8; ++nt) {
                const int c0 = wn * 64 + nt * 8 + 2 * tig;
                *(float2*)&Sc[r0 * SCP + c0] =
                    make_float2(acc[mt][nt][0], acc[mt][nt][1]);
                *(float2*)&Sc[(r0 + 8) * SCP + c0] =
                    make_float2(acc[mt][nt][2], acc[mt][nt][3]);
            }
        }
        __syncthreads();

        // scan: key = sq[j] - 2*dot (sq[i] constant per row)
        const float* srcrow = &Sc[srow * SCP + shalf * 64];
        const float* sqrow  = &sqs[shalf * 64];
        const int jbase = j0 + shalf * 64;
        for (int s = 0; s < 64; ++s) {
            int j = jbase + s;
            float key = sqrow[s] - 2.0f * srcrow[s];
            if (j != ig && key < ts[0]) {
                ts[0] = key; ti[0] = j;
#pragma unroll
                for (int t2 = 0; t2 < KB - 1; ++t2) {
                    if (ts[t2] < ts[t2 + 1]) {
                        float tf = ts[t2]; ts[t2] = ts[t2 + 1]; ts[t2 + 1] = tf;
                        int   tn = ti[t2]; ti[t2] = ti[t2 + 1]; ti[t2 + 1] = tn;
                    }
                }
            }
        }
        __syncthreads();  // Sc/sqs reusable next tile
    }

    // write 16 candidates per half (rescore picks exact top-8)
    {
        int base = ((b * NN + ig) * 2 + shalf) * KB;
#pragma unroll
        for (int k = 0; k < KB; ++k) g_cand[base + k] = ti[k];
    }
}

// ---------------------------------------------------------------------------
// Kernel 4: fused exact rescore (32 cand -> top-8) + aggregation + LayerNorm.
// 256 threads = 8 warps, one node per warp; smem transpose for coalesced out.
// Lane l owns channels [8l, 8l+8).
// ---------------------------------------------------------------------------
__global__ __launch_bounds__(256) void k_refine(const float* __restrict__ gamma,
                                                const float* __restrict__ beta,
                                                float* __restrict__ out) {
    const int b    = blockIdx.y;
    const int wid  = threadIdx.x >> 5;
    const int lane = threadIdx.x & 31;
    const int n0   = blockIdx.x * 8;
    const int n    = n0 + wid;
    const int h = n / WW, w = n % WW;
    const float* Nb = g_nodesT + (size_t)b * NN * CC;

    const float* xi = Nb + (size_t)n * CC + lane * 8;
    float4 x0 = *(const float4*)xi;
    float4 x1 = *(const float4*)(xi + 4);

    // ---- exact rescore of 32 candidates (one per lane) ----
    int cand = g_cand[(b * NN + n) * NCAND + lane];
    float mykey = 3.0e38f;
    int   myidx = cand;
#pragma unroll
    for (int k = 0; k < NCAND; ++k) {
        int j = __shfl_sync(0xffffffffu, cand, k);
        const float* xj = Nb + (size_t)j * CC + lane * 8;
        float4 y0 = *(const float4*)xj;
        float4 y1 = *(const float4*)(xj + 4);
        float p = x0.x * y0.x + x0.y * y0.y + x0.z * y0.z + x0.w * y0.w
                + x1.x * y1.x + x1.y * y1.y + x1.z * y1.z + x1.w * y1.w;
#pragma unroll
        for (int o = 16; o > 0; o >>= 1) p += __shfl_xor_sync(0xffffffffu, p, o);
        if (lane == k) mykey = g_sq[b * NN + j] - 2.0f * p;
    }

    // ---- select 8 smallest; indices broadcast to all lanes ----
    int knn_j[KNN];
#pragma unroll
    for (int t = 0; t < KNN; ++t) {
        float v = mykey;
#pragma unroll
        for (int o = 16; o > 0; o >>= 1) v = fminf(v, __shfl_xor_sync(0xffffffffu, v, o));
        unsigned m = __ballot_sync(0xffffffffu, mykey == v);
        int src = __ffs(m) - 1;
        knn_j[t] = __shfl_sync(0xffffffffu, myidx, src);
        if (lane == src) mykey = 3.0e38f;
    }

    // ---- aggregate: 4-neighborhood grid + 8 knn, mean; residual ----
    float acc[8];
#pragma unroll
    for (int r = 0; r < 8; ++r) acc[r] = 0.f;
    int cnt = KNN;
#pragma unroll
    for (int t = 0; t < KNN; ++t) {
        const float* p = Nb + (size_t)knn_j[t] * CC + lane * 8;
        float4 y0 = *(const float4*)p;
        float4 y1 = *(const float4*)(p + 4);
        acc[0] += y0.x; acc[1] += y0.y; acc[2] += y0.z; acc[3] += y0.w;
        acc[4] += y1.x; acc[5] += y1.y; acc[6] += y1.z; acc[7] += y1.w;
    }
    if (w > 0)      { const float* p = Nb + (size_t)(n - 1)  * CC + lane * 8;
        float4 y0 = *(const float4*)p; float4 y1 = *(const float4*)(p + 4);
        acc[0]+=y0.x; acc[1]+=y0.y; acc[2]+=y0.z; acc[3]+=y0.w;
        acc[4]+=y1.x; acc[5]+=y1.y; acc[6]+=y1.z; acc[7]+=y1.w; cnt++; }
    if (w < WW - 1) { const float* p = Nb + (size_t)(n + 1)  * CC + lane * 8;
        float4 y0 = *(const float4*)p; float4 y1 = *(const float4*)(p + 4);
        acc[0]+=y0.x; acc[1]+=y0.y; acc[2]+=y0.z; acc[3]+=y0.w;
        acc[4]+=y1.x; acc[5]+=y1.y; acc[6]+=y1.z; acc[7]+=y1.w; cnt++; }
    if (h > 0)      { const float* p = Nb + (size_t)(n - WW) * CC + lane * 8;
        float4 y0 = *(const float4*)p; float4 y1 = *(const float4*)(p + 4);
        acc[0]+=y0.x; acc[1]+=y0.y; acc[2]+=y0.z; acc[3]+=y0.w;
        acc[4]+=y1.x; acc[5]+=y1.y; acc[6]+=y1.z; acc[7]+=y1.w; cnt++; }
    if (h < HH - 1) { const float* p = Nb + (size_t)(n + WW) * CC + lane * 8;
        float4 y0 = *(const float4*)p; float4 y1 = *(const float4*)(p + 4);
        acc[0]+=y0.x; acc[1]+=y0.y; acc[2]+=y0.z; acc[3]+=y0.w;
        acc[4]+=y1.x; acc[5]+=y1.y; acc[6]+=y1.z; acc[7]+=y1.w; cnt++; }

    const float inv = 1.0f / (float)cnt;
    float xv[8] = {x0.x, x0.y, x0.z, x0.w, x1.x, x1.y, x1.z, x1.w};
    float y[8];
#pragma unroll
    for (int r = 0; r < 8; ++r) y[r] = acc[r] * inv + xv[r];

    // ---- LayerNorm over channels ----
    float s = 0.f;
#pragma unroll
    for (int r = 0; r < 8; ++r) s += y[r];
#pragma unroll
    for (int o = 16; o > 0; o >>= 1) s += __shfl_xor_sync(0xffffffffu, s, o);
    const float mu = s * (1.0f / CC);
    float v = 0.f;
#pragma unroll
    for (int r = 0; r < 8; ++r) { float d = y[r] - mu; v += d * d; }
#pragma unroll
    for (int o = 16; o > 0; o >>= 1) v += __shfl_xor_sync(0xffffffffu, v, o);
    const float rs = rsqrtf(v * (1.0f / CC) + 1e-5f);

    __shared__ float st[8][CC];
#pragma unroll
    for (int r = 0; r < 8; ++r) {
        int c = lane * 8 + r;
        st[wid][c] = (y[r] - mu) * rs * gamma[c] + beta[c];
    }
    __syncthreads();

    // coalesced write: thread = channel, 8 consecutive n per thread
    const int c = threadIdx.x;
    float4 v0 = make_float4(st[0][c], st[1][c], st[2][c], st[3][c]);
    float4 v1 = make_float4(st[4][c], st[5][c], st[6][c], st[7][c]);
    size_t o = (size_t)b * CC * NN + (size_t)c * NN + n0;
    *(float4*)&out[o]     = v0;
    *(float4*)&out[o + 4] = v1;
}

// ---------------------------------------------------------------------------
extern "C" void kernel_launch(void* const* d_in, const int* in_sizes, int n_in,
                              void* d_out, int out_size) {
    const float* F     = (const float*)d_in[0];
    const float* gamma = (const float*)d_in[1];
    const float* beta  = (const float*)d_in[2];
    float* out = (float*)d_out;
    (void)in_sizes; (void)n_in; (void)out_size;

    k_transpose<<<dim3(NN / 32, CC / 32, BQ), dim3(32, 8)>>>(F);
    k_sq<<<(BQ * NN + 255) / 256, 256>>>(F);

    cudaFuncSetAttribute(k_gram_topk_mma,
                         cudaFuncAttributeMaxDynamicSharedMemorySize, SMB_TOT);
    k_gram_topk_mma<<<dim3(NTILES, BQ), 256, SMB_TOT>>>();

    k_refine<<<dim3(NN / 8, BQ), 256>>>(gamma, beta, out);
}